// round 8
// baseline (speedup 1.0000x reference)
#include <cuda_runtime.h>
#include <cuda_bf16.h>
#include <cstdint>

// QuantizedEmbedding: out[i, d] = code[quant_weight[x[i], d]] * absmax[x[i] >> 2]
//   x: int32[16384]  qw: int32[50304,1024]  absmax: f32[12576]  code: f32[256]
//   out: f32[16384,1024]   (block index == v>>2 since (v%4)*1024 + d < 4096)
//
// R8 = R6's zero-conflict lane-private codebook (s[q*32+lane] -> bank==lane
// for any q) AT HIGH OCCUPANCY (the combination never tried):
//   - TOK=16 tokens/CTA amortizes the 32KB table fill (1024 CTAs)
//   - inner pipeline in chunks of 2 tokens (prefetch next chunk while
//     processing current): low regs (-> occ 6) and low MLP_p1 (less
//     L1tex-queue overflow spread)

#define TOK   16
#define CHUNK 2
#define NCHUNK (TOK / CHUNK)

__global__ void __launch_bounds__(256, 6)
qembed_kernel(const int* __restrict__ x,
              const int4* __restrict__ qw,
              const float* __restrict__ absmax,
              const float* __restrict__ code,
              float4* __restrict__ out)
{
    __shared__ float s_code[256 * 32];     // lane-private: zero LDS conflicts
    const int t    = threadIdx.x;
    const int lane = t & 31;
    const int tok0 = blockIdx.x * TOK;

    // Prefetch chunk 0 BEFORE the smem fill so the fill hides load latency.
    int4  q[CHUNK];
    float sc[CHUNK];
    {
        const int v0 = x[tok0 + 0];
        const int v1 = x[tok0 + 1];
        q[0]  = qw[(size_t)v0 * 256 + t];
        q[1]  = qw[(size_t)v1 * 256 + t];
        sc[0] = __ldg(&absmax[v0 >> 2]);
        sc[1] = __ldg(&absmax[v1 >> 2]);
    }

    // Fill 32x replicated codebook: word i -> bank i%32, conflict-free.
    #pragma unroll 8
    for (int i = t; i < 256 * 32; i += 256)
        s_code[i] = code[i >> 5];
    __syncthreads();

    #pragma unroll
    for (int c = 0; c < NCHUNK; c++) {
        int4  qn[CHUNK];
        float scn[CHUNK];
        if (c + 1 < NCHUNK) {
            // Prefetch next chunk's independent loads before processing.
            const int w0 = x[tok0 + (c + 1) * CHUNK + 0];
            const int w1 = x[tok0 + (c + 1) * CHUNK + 1];
            qn[0]  = qw[(size_t)w0 * 256 + t];
            qn[1]  = qw[(size_t)w1 * 256 + t];
            scn[0] = __ldg(&absmax[w0 >> 2]);
            scn[1] = __ldg(&absmax[w1 >> 2]);
        }

        #pragma unroll
        for (int k = 0; k < CHUNK; k++) {
            float4 o;
            o.x = s_code[q[k].x * 32 + lane] * sc[k];
            o.y = s_code[q[k].y * 32 + lane] * sc[k];
            o.z = s_code[q[k].z * 32 + lane] * sc[k];
            o.w = s_code[q[k].w * 32 + lane] * sc[k];
            __stcs(&out[(size_t)(tok0 + c * CHUNK + k) * 256 + t], o);
        }

        #pragma unroll
        for (int k = 0; k < CHUNK; k++) { q[k] = qn[k]; sc[k] = scn[k]; }
    }
}

extern "C" void kernel_launch(void* const* d_in, const int* in_sizes, int n_in,
                              void* d_out, int out_size)
{
    // Bind inputs by element count (all four distinct) — robust to ordering.
    const int*   x      = nullptr;  int n_tokens = 0;
    const int4*  qw     = nullptr;
    const float* absmax = nullptr;
    const float* code   = nullptr;

    for (int i = 0; i < n_in; i++) {
        const int sz = in_sizes[i];
        if (sz == 256)            code   = (const float*)d_in[i];
        else if (sz == 12576)     absmax = (const float*)d_in[i];
        else if (sz > 1000000)    qw     = (const int4*)d_in[i];
        else                      { x = (const int*)d_in[i]; n_tokens = sz; }
    }

    float4* out = (float4*)d_out;
    const int n_cta = n_tokens / TOK;   // 1024
    qembed_kernel<<<n_cta, 256>>>(x, qw, absmax, code, out);
}